// round 1
// baseline (speedup 1.0000x reference)
#include <cuda_runtime.h>
#include <cuda_bf16.h>

#define N_NODES 8192
#define FLOW_ITERS 10

// Scratch state: adj (current relu'd node potential) and inflow accumulator.
__device__ float g_adj[N_NODES];
__device__ float g_inflow[N_NODES];

// adj_1 = relu(-d); inflow = 0
__global__ void k_init(const float* __restrict__ demands) {
    int i = blockIdx.x * blockDim.x + threadIdx.x;
    if (i < N_NODES) {
        float d = demands[i];
        g_adj[i] = fmaxf(-d, 0.0f);
        g_inflow[i] = 0.0f;
    }
}

// inflow[cols[e]] += values[e] * adj[rows[e]]   (4 edges per thread, vectorized loads)
__global__ void k_scatter(const int* __restrict__ rows,
                          const int* __restrict__ cols,
                          const float* __restrict__ values,
                          int e4) {
    int t = blockIdx.x * blockDim.x + threadIdx.x;
    if (t < e4) {
        int4   r = __ldg(((const int4*)rows) + t);
        int4   c = __ldg(((const int4*)cols) + t);
        float4 v = __ldg(((const float4*)values) + t);
        atomicAdd(&g_inflow[c.x], v.x * __ldg(&g_adj[r.x]));
        atomicAdd(&g_inflow[c.y], v.y * __ldg(&g_adj[r.y]));
        atomicAdd(&g_inflow[c.z], v.z * __ldg(&g_adj[r.z]));
        atomicAdd(&g_inflow[c.w], v.w * __ldg(&g_adj[r.w]));
    }
}

// adj = relu(inflow - d); inflow = 0
__global__ void k_update(const float* __restrict__ demands) {
    int i = blockIdx.x * blockDim.x + threadIdx.x;
    if (i < N_NODES) {
        g_adj[i] = fmaxf(g_inflow[i] - demands[i], 0.0f);
        g_inflow[i] = 0.0f;
    }
}

// zero the 256MB output with vectorized grid-stride stores
__global__ void k_zero(float4* __restrict__ out, int n4) {
    int stride = gridDim.x * blockDim.x;
    float4 z = make_float4(0.f, 0.f, 0.f, 0.f);
    for (int i = blockIdx.x * blockDim.x + threadIdx.x; i < n4; i += stride)
        out[i] = z;
}

// out[rows[e], cols[e]] += values[e] * adj_final[rows[e]]
__global__ void k_final(const int* __restrict__ rows,
                        const int* __restrict__ cols,
                        const float* __restrict__ values,
                        float* __restrict__ out,
                        int e4) {
    int t = blockIdx.x * blockDim.x + threadIdx.x;
    if (t < e4) {
        int4   r = __ldg(((const int4*)rows) + t);
        int4   c = __ldg(((const int4*)cols) + t);
        float4 v = __ldg(((const float4*)values) + t);
        atomicAdd(out + (size_t)r.x * N_NODES + c.x, v.x * __ldg(&g_adj[r.x]));
        atomicAdd(out + (size_t)r.y * N_NODES + c.y, v.y * __ldg(&g_adj[r.y]));
        atomicAdd(out + (size_t)r.z * N_NODES + c.z, v.z * __ldg(&g_adj[r.z]));
        atomicAdd(out + (size_t)r.w * N_NODES + c.w, v.w * __ldg(&g_adj[r.w]));
    }
}

extern "C" void kernel_launch(void* const* d_in, const int* in_sizes, int n_in,
                              void* d_out, int out_size) {
    const float* values  = (const float*)d_in[0];
    const float* demands = (const float*)d_in[1];
    const int*   rows    = (const int*)d_in[2];
    const int*   cols    = (const int*)d_in[3];
    float*       out     = (float*)d_out;

    int E  = in_sizes[0];       // 262144
    int e4 = E / 4;             // 65536
    int n4 = out_size / 4;      // 16777216

    // Zero the big output first (independent of the flow iterations).
    k_zero<<<2048, 256>>>((float4*)out, n4);

    // adj_1 = relu(-d)
    k_init<<<(N_NODES + 255) / 256, 256>>>(demands);

    // 9 more iterations -> adj_10
    for (int it = 1; it < FLOW_ITERS; ++it) {
        k_scatter<<<(e4 + 255) / 256, 256>>>(rows, cols, values, e4);
        k_update<<<(N_NODES + 255) / 256, 256>>>(demands);
    }

    // flow_10 = values * adj_10[rows], scattered into the dense output
    k_final<<<(e4 + 255) / 256, 256>>>(rows, cols, values, out, e4);
}